// round 8
// baseline (speedup 1.0000x reference)
#include <cuda_runtime.h>

#define BB 32
#define NN 4096
#define DD 1024
#define HH 16

// Scratch (device globals)
__device__ float  g_qp[4][BB * DD];          // q projection partials over 4 d-ranges
__device__ float  g_Ut[BB * DD * HH];        // folded key vectors, transposed [b][d][h] (scaled 1/8)
__device__ float  g_att[BB * HH * NN];       // RAW scores
__device__ float2 g_stat[BB * HH * 32];      // per-(b,h,128n-tile) (max, sumexp)
__device__ float  g_wp[8][BB * HH * DD];     // partial attn@value over 8 n-segments

typedef unsigned long long u64;

__device__ __forceinline__ void fma2(u64 &d, u64 a, u64 b) {
    asm("fma.rn.f32x2 %0, %1, %2, %0;" : "+l"(d) : "l"(a), "l"(b));
}
__device__ __forceinline__ u64 pack2(float lo, float hi) {
    u64 r; asm("mov.b64 %0, {%1, %2};" : "=l"(r) : "f"(lo), "f"(hi)); return r;
}
__device__ __forceinline__ void unpack2(u64 v, float &lo, float &hi) {
    asm("mov.b64 {%0, %1}, %2;" : "=f"(lo), "=f"(hi) : "l"(v));
}
__device__ __forceinline__ unsigned smem_u32(const void* p) {
    return (unsigned)__cvta_generic_to_shared(p);
}
__device__ __forceinline__ void cpasync16(unsigned dst, const void* src) {
    asm volatile("cp.async.cg.shared.global [%0], [%1], 16;\n" :: "r"(dst), "l"(src));
}
#define CP_COMMIT() asm volatile("cp.async.commit_group;\n" ::: "memory")
#define CP_WAIT(n)  asm volatile("cp.async.wait_group %0;\n" :: "n"(n) : "memory")

// ---------------------------------------------------------------------------
// Kernel A: qp[dsp][b,c] = sum_{d in dsp-range(256)} query[b,d] * wq[d,c]
// Also zeroes d_out (256 blocks x 128 threads = 32768 floats exactly).
// ---------------------------------------------------------------------------
__global__ __launch_bounds__(128) void k_qproj(const float* __restrict__ query,
                                               const float* __restrict__ wq,
                                               float* __restrict__ out) {
    const int tx  = threadIdx.x;
    const int c0  = blockIdx.x * 128;
    const int b0  = blockIdx.y * 4;
    const int dsp = blockIdx.z;
    const int dr0 = dsp * 256;

    {
        int lin = blockIdx.x + 8 * blockIdx.y + 64 * blockIdx.z;
        out[lin * 128 + tx] = 0.0f;
    }

    __shared__ __align__(16) float sq[4][256];
#pragma unroll
    for (int i = 0; i < 2; i++) {
        int fl = i * 128 + tx;
        int bb = fl >> 6, d4 = fl & 63;
        *(float4*)&sq[bb][d4 * 4] =
            *(const float4*)(query + (size_t)(b0 + bb) * DD + dr0 + d4 * 4);
    }
    __syncthreads();

    u64 acc[4] = {0ull, 0ull, 0ull, 0ull};
    const float* wc = wq + (size_t)dr0 * DD + c0 + tx;
#pragma unroll 16
    for (int d = 0; d < 256; d += 2) {
        float w0 = wc[(size_t)d * DD];
        float w1 = wc[(size_t)(d + 1) * DD];
        u64 w2 = pack2(w0, w1);
#pragma unroll
        for (int bb = 0; bb < 4; bb++) {
            u64 q2 = *(const u64*)&sq[bb][d];
            fma2(acc[bb], q2, w2);
        }
    }
#pragma unroll
    for (int bb = 0; bb < 4; bb++) {
        float lo, hi; unpack2(acc[bb], lo, hi);
        g_qp[dsp][(size_t)(b0 + bb) * DD + c0 + tx] = lo + hi;
    }
}

// ---------------------------------------------------------------------------
// Kernel B: Ut[b,d,h] = (1/8) * sum_{c<64} wk[d, h*64+c] * q[b, h*64+c]
// ---------------------------------------------------------------------------
__global__ __launch_bounds__(128) void k_uproj(const float* __restrict__ wk) {
    const int tx = threadIdx.x;
    const int d0 = blockIdx.x * 128;
    const int h  = blockIdx.y;
    __shared__ __align__(16) float4 swk4[128 * 17];
    __shared__ __align__(16) float  sq[32][64];

#pragma unroll
    for (int i = 0; i < 16; i++) {
        int fl = i * 128 + tx;
        int r  = fl >> 4, c4 = fl & 15;
        swk4[r * 17 + c4] =
            *(const float4*)(wk + (size_t)(d0 + r) * DD + h * 64 + c4 * 4);
    }
#pragma unroll
    for (int i = 0; i < 4; i++) {
        int fl = i * 128 + tx;
        int bb = fl >> 4, c4 = fl & 15;
        float4 s = *(const float4*)(g_qp[0] + (size_t)bb * DD + h * 64 + c4 * 4);
#pragma unroll
        for (int p = 1; p < 4; p++) {
            float4 a = *(const float4*)(g_qp[p] + (size_t)bb * DD + h * 64 + c4 * 4);
            s.x += a.x; s.y += a.y; s.z += a.z; s.w += a.w;
        }
        *(float4*)&sq[bb][c4 * 4] = s;
    }
    __syncthreads();

    ulonglong2 wreg[16];
#pragma unroll
    for (int c4 = 0; c4 < 16; c4++)
        wreg[c4] = *(const ulonglong2*)&swk4[tx * 17 + c4];

    const int dst_base = (d0 + tx) * HH + h;
#pragma unroll 2
    for (int bb = 0; bb < 32; bb++) {
        u64 a2 = 0ull;
#pragma unroll
        for (int c4 = 0; c4 < 16; c4++) {
            ulonglong2 q2 = *(const ulonglong2*)&sq[bb][c4 * 4];
            fma2(a2, wreg[c4].x, q2.x);
            fma2(a2, wreg[c4].y, q2.y);
        }
        float lo, hi; unpack2(a2, lo, hi);
        g_Ut[(size_t)bb * (DD * HH) + dst_base] = (lo + hi) * 0.125f;
    }
}

// ---------------------------------------------------------------------------
// Kernel C: raw scores + per-warp-tile softmax stats.
// scores[b,h,n] = sum_d key[b,n,d] * Ut[b,d,h]   (streams key 512MB)
// 64-thr CTAs (2 warps); warp owns 128 n; thread owns 4 n.
// Epilogue: per head, warp-reduce (max, sumexp) over the 128-n tile
//           -> g_stat[(b*HH+h)*32 + tile].
// ---------------------------------------------------------------------------
__global__ __launch_bounds__(64, 5) void k_scores(const float* __restrict__ key) {
    const int tx   = threadIdx.x;
    const int w    = tx >> 5;
    const int l    = tx & 31;
    const int b    = blockIdx.y;
    const int n0   = blockIdx.x * 256;
    const int nwrp = n0 + w * 128;

    __shared__ __align__(16) float4 skW[2][2][128 * 5];
    __shared__ __align__(16) float4 sUW[2][2][64];

    const float* keyw = key + ((size_t)b * NN + nwrp) * DD;
    const float* Utb  = g_Ut + (size_t)b * (DD * HH);

    u64 acc[4][8];
#pragma unroll
    for (int n4 = 0; n4 < 4; n4++)
#pragma unroll
        for (int p = 0; p < 8; p++) acc[n4][p] = 0ull;

    {
#pragma unroll
        for (int i = 0; i < 16; i++) {
            int fl = i * 32 + l;
            int n = fl >> 2, q4 = fl & 3;
            cpasync16(smem_u32(&skW[w][0][n * 5 + q4]),
                      keyw + (size_t)n * DD + q4 * 4);
        }
#pragma unroll
        for (int j = 0; j < 2; j++)
            cpasync16(smem_u32(&sUW[w][0][j * 32 + l]), Utb + (j * 32 + l) * 4);
        CP_COMMIT();
    }

#pragma unroll 1
    for (int ch = 0; ch < 64; ch++) {
        if (ch + 1 < 64) {
            const int st = (ch + 1) & 1, d0 = (ch + 1) * 16;
#pragma unroll
            for (int i = 0; i < 16; i++) {
                int fl = i * 32 + l;
                int n = fl >> 2, q4 = fl & 3;
                cpasync16(smem_u32(&skW[w][st][n * 5 + q4]),
                          keyw + (size_t)n * DD + d0 + q4 * 4);
            }
#pragma unroll
            for (int j = 0; j < 2; j++)
                cpasync16(smem_u32(&sUW[w][st][j * 32 + l]),
                          Utb + d0 * HH + (j * 32 + l) * 4);
            CP_COMMIT();
            CP_WAIT(1);
        } else {
            CP_WAIT(0);
        }
        __syncwarp();

        const int st = ch & 1;
#pragma unroll
        for (int g = 0; g < 4; g++) {
            float4 kv[4];
#pragma unroll
            for (int n4 = 0; n4 < 4; n4++)
                kv[n4] = skW[w][st][(n4 * 32 + l) * 5 + g];
#pragma unroll
            for (int s = 0; s < 4; s++) {
                int dd = g * 4 + s;
                const ulonglong2* uv = (const ulonglong2*)&sUW[w][st][dd * 4];
                ulonglong2 u0 = uv[0], u1 = uv[1];
                ulonglong2 u2 = uv[2], u3 = uv[3];
#pragma unroll
                for (int n4 = 0; n4 < 4; n4++) {
                    float kvs = (s == 0) ? kv[n4].x : (s == 1) ? kv[n4].y
                              : (s == 2) ? kv[n4].z : kv[n4].w;
                    u64 kv2 = pack2(kvs, kvs);
                    fma2(acc[n4][0], u0.x, kv2);
                    fma2(acc[n4][1], u0.y, kv2);
                    fma2(acc[n4][2], u1.x, kv2);
                    fma2(acc[n4][3], u1.y, kv2);
                    fma2(acc[n4][4], u2.x, kv2);
                    fma2(acc[n4][5], u2.y, kv2);
                    fma2(acc[n4][6], u3.x, kv2);
                    fma2(acc[n4][7], u3.y, kv2);
                }
            }
        }
        __syncwarp();
    }

    // write raw scores
#pragma unroll
    for (int n4 = 0; n4 < 4; n4++) {
#pragma unroll
        for (int p = 0; p < 8; p++) {
            float lo, hi;
            unpack2(acc[n4][p], lo, hi);
            g_att[((size_t)b * HH + 2 * p)     * NN + nwrp + n4 * 32 + l] = lo;
            g_att[((size_t)b * HH + 2 * p + 1) * NN + nwrp + n4 * 32 + l] = hi;
        }
    }

    // epilogue: per-head (max, sumexp) over this warp's 128-n tile
    float mt[16];
#pragma unroll
    for (int h = 0; h < 16; h++) mt[h] = -3e38f;
#pragma unroll
    for (int n4 = 0; n4 < 4; n4++)
#pragma unroll
        for (int p = 0; p < 8; p++) {
            float lo, hi; unpack2(acc[n4][p], lo, hi);
            mt[2 * p]     = fmaxf(mt[2 * p], lo);
            mt[2 * p + 1] = fmaxf(mt[2 * p + 1], hi);
        }
#pragma unroll
    for (int h = 0; h < 16; h++)
#pragma unroll
        for (int o = 16; o; o >>= 1)
            mt[h] = fmaxf(mt[h], __shfl_xor_sync(0xffffffffu, mt[h], o));

    float st[16];
#pragma unroll
    for (int h = 0; h < 16; h++) st[h] = 0.f;
#pragma unroll
    for (int n4 = 0; n4 < 4; n4++)
#pragma unroll
        for (int p = 0; p < 8; p++) {
            float lo, hi; unpack2(acc[n4][p], lo, hi);
            st[2 * p]     += __expf(lo - mt[2 * p]);
            st[2 * p + 1] += __expf(hi - mt[2 * p + 1]);
        }
#pragma unroll
    for (int h = 0; h < 16; h++)
#pragma unroll
        for (int o = 16; o; o >>= 1)
            st[h] += __shfl_xor_sync(0xffffffffu, st[h], o);

    if (l == 0) {
        int wtile = blockIdx.x * 2 + w;
#pragma unroll
        for (int h = 0; h < 16; h++)
            g_stat[((size_t)b * HH + h) * 32 + wtile] = make_float2(mt[h], st[h]);
    }
}

// ---------------------------------------------------------------------------
// Kernel E: wp[seg][b,h,d] = sum_{n in seg(512)} softmax(att)[b,h,n]*value[b,n,d]
// Softmax applied during staging from tile stats (g_stat).
// grid (2 d-tiles of 512, 8 seg, 32 b), 128 thr; thread owns 4 consecutive d.
// 8-deep float4 register pipeline on value.
// ---------------------------------------------------------------------------
__global__ __launch_bounds__(128, 4) void k_wpart(const float* __restrict__ value) {
    const int tx  = threadIdx.x;
    const int d0  = blockIdx.x * 512;
    const int seg = blockIdx.y;
    const int b   = blockIdx.z;

    __shared__ __align__(16) float sA[512 * 20];   // [n][16h + 4 pad], 40KB
    __shared__ float2 sMS[16];                     // (m_glob, 1/s_glob) per head

    // global softmax stats from 32 tile-stats per row
    if (tx < 16) {
        const float2* gs = g_stat + ((size_t)b * HH + tx) * 32;
        float m = -3e38f;
#pragma unroll
        for (int t = 0; t < 32; t++) m = fmaxf(m, gs[t].x);
        float s = 0.f;
#pragma unroll
        for (int t = 0; t < 32; t++) {
            float2 p = gs[t];
            s += p.y * __expf(p.x - m);
        }
        sMS[tx] = make_float2(m, 1.f / s);
    }
    __syncthreads();

    const float* attb = g_att + (size_t)b * HH * NN + seg * 512;
#pragma unroll
    for (int i = 0; i < 16; i++) {
        int fl = i * 128 + tx;
        int h = fl >> 7, n4 = (fl & 127) * 4;
        float4 a = *(const float4*)(attb + (size_t)h * NN + n4);
        float2 ms = sMS[h];
        sA[(n4 + 0) * 20 + h] = __expf(a.x - ms.x) * ms.y;
        sA[(n4 + 1) * 20 + h] = __expf(a.y - ms.x) * ms.y;
        sA[(n4 + 2) * 20 + h] = __expf(a.z - ms.x) * ms.y;
        sA[(n4 + 3) * 20 + h] = __expf(a.w - ms.x) * ms.y;
    }
    __syncthreads();

    u64 acc[32];   // acc[dd*8+hp], dd in 0..3 (4 owned d), hp in 0..7
#pragma unroll
    for (int p = 0; p < 32; p++) acc[p] = 0ull;

    const float* valb = value + ((size_t)b * NN + seg * 512) * DD + d0 + tx * 4;

    float4 vc[8], vn[8];
#pragma unroll
    for (int j = 0; j < 8; j++)
        vc[j] = *(const float4*)(valb + (size_t)j * DD);

#pragma unroll 1
    for (int n = 0; n < 512; n += 8) {
        if (n + 8 < 512) {
#pragma unroll
            for (int j = 0; j < 8; j++)
                vn[j] = *(const float4*)(valb + (size_t)(n + 8 + j) * DD);
        }
#pragma unroll
        for (int j = 0; j < 8; j++) {
            float vs[4] = {vc[j].x, vc[j].y, vc[j].z, vc[j].w};
            const ulonglong2* av = (const ulonglong2*)&sA[(n + j) * 20];
            ulonglong2 a0 = av[0], a1 = av[1], a2 = av[2], a3 = av[3];
#pragma unroll
            for (int dd = 0; dd < 4; dd++) {
                u64 v2 = pack2(vs[dd], vs[dd]);
                fma2(acc[dd * 8 + 0], a0.x, v2);
                fma2(acc[dd * 8 + 1], a0.y, v2);
                fma2(acc[dd * 8 + 2], a1.x, v2);
                fma2(acc[dd * 8 + 3], a1.y, v2);
                fma2(acc[dd * 8 + 4], a2.x, v2);
                fma2(acc[dd * 8 + 5], a2.y, v2);
                fma2(acc[dd * 8 + 6], a3.x, v2);
                fma2(acc[dd * 8 + 7], a3.y, v2);
            }
        }
#pragma unroll
        for (int j = 0; j < 8; j++) vc[j] = vn[j];
    }

#pragma unroll
    for (int hp = 0; hp < 8; hp++) {
        float l0, h0x, l1, h1x, l2, h2x, l3, h3x;
        unpack2(acc[0 * 8 + hp], l0, h0x);
        unpack2(acc[1 * 8 + hp], l1, h1x);
        unpack2(acc[2 * 8 + hp], l2, h2x);
        unpack2(acc[3 * 8 + hp], l3, h3x);
        float4 olo = make_float4(l0, l1, l2, l3);
        float4 ohi = make_float4(h0x, h1x, h2x, h3x);
        *(float4*)(g_wp[seg] + ((size_t)b * HH + 2 * hp)     * DD + d0 + tx * 4) = olo;
        *(float4*)(g_wp[seg] + ((size_t)b * HH + 2 * hp + 1) * DD + d0 + tx * 4) = ohi;
    }
}

// ---------------------------------------------------------------------------
// Kernel F: out[b,c] += sum_{d in dsp-range(256)} w[b, c>>6, d] * wv[d, c]
// (w assembled on the fly from the 8 wpart partials)
// ---------------------------------------------------------------------------
__global__ __launch_bounds__(128) void k_oproj(const float* __restrict__ wv,
                                               float* __restrict__ out) {
    const int tx  = threadIdx.x;
    const int c0  = blockIdx.x * 128;
    const int b0  = blockIdx.y * 4;
    const int dsp = blockIdx.z;
    const int dr0 = dsp * 256;
    const int h0  = c0 >> 6;
    __shared__ __align__(16) float sw[4][2][256];

#pragma unroll
    for (int i = 0; i < 4; i++) {
        int fl = i * 128 + tx;
        int bb = fl >> 7, hh = (fl >> 6) & 1, d4 = fl & 63;
        size_t gidx = ((size_t)(b0 + bb) * HH + h0 + hh) * DD + dr0 + d4 * 4;
        float4 s = *(const float4*)(g_wp[0] + gidx);
#pragma unroll
        for (int p = 1; p < 8; p++) {
            float4 a = *(const float4*)(g_wp[p] + gidx);
            s.x += a.x; s.y += a.y; s.z += a.z; s.w += a.w;
        }
        *(float4*)&sw[bb][hh][d4 * 4] = s;
    }
    __syncthreads();

    const int hin = tx >> 6;
    u64 acc[4] = {0ull, 0ull, 0ull, 0ull};
    const float* wc = wv + (size_t)dr0 * DD + c0 + tx;
#pragma unroll 16
    for (int dd = 0; dd < 256; dd += 2) {
        float w0 = wc[(size_t)dd * DD];
        float w1 = wc[(size_t)(dd + 1) * DD];
        u64 w2 = pack2(w0, w1);
#pragma unroll
        for (int bb = 0; bb < 4; bb++) {
            u64 s2 = *(const u64*)&sw[bb][hin][dd];
            fma2(acc[bb], s2, w2);
        }
    }
#pragma unroll
    for (int bb = 0; bb < 4; bb++) {
        float lo, hi; unpack2(acc[bb], lo, hi);
        atomicAdd(&out[(size_t)(b0 + bb) * DD + c0 + tx], lo + hi);
    }
}

// ---------------------------------------------------------------------------
extern "C" void kernel_launch(void* const* d_in, const int* in_sizes, int n_in,
                              void* d_out, int out_size) {
    const float* query = (const float*)d_in[0];
    const float* key   = (const float*)d_in[1];
    const float* value = (const float*)d_in[2];
    const float* wq    = (const float*)d_in[3];
    const float* wk    = (const float*)d_in[4];
    const float* wv    = (const float*)d_in[5];
    float* out = (float*)d_out;

    k_qproj  <<<dim3(8, 8, 4),  128>>>(query, wq, out);
    k_uproj  <<<dim3(8, HH),    128>>>(wk);
    k_scores <<<dim3(16, BB),   64>>>(key);
    k_wpart  <<<dim3(2, 8, BB), 128>>>(value);   // 4th launch -> profiled
    k_oproj  <<<dim3(8, 8, 4),  128>>>(wv, out);
}

// round 9
// speedup vs baseline: 1.0207x; 1.0207x over previous
#include <cuda_runtime.h>

#define BB 32
#define NN 4096
#define DD 1024
#define HH 16

// Scratch (device globals)
__device__ float  g_qp[4][BB * DD];          // q projection partials over 4 d-ranges
__device__ float  g_Ut[BB * DD * HH];        // folded key vectors, transposed [b][d][h] (scaled 1/8)
__device__ float  g_att[BB * HH * NN];       // RAW scores
__device__ float2 g_stat[BB * HH * 32];      // per-(b,h,128n-tile) (max, sumexp)
__device__ float  g_wp[8][BB * HH * DD];     // partial attn@value over 8 n-segments

typedef unsigned long long u64;

__device__ __forceinline__ void fma2(u64 &d, u64 a, u64 b) {
    asm("fma.rn.f32x2 %0, %1, %2, %0;" : "+l"(d) : "l"(a), "l"(b));
}
__device__ __forceinline__ u64 pack2(float lo, float hi) {
    u64 r; asm("mov.b64 %0, {%1, %2};" : "=l"(r) : "f"(lo), "f"(hi)); return r;
}
__device__ __forceinline__ void unpack2(u64 v, float &lo, float &hi) {
    asm("mov.b64 {%0, %1}, %2;" : "=f"(lo), "=f"(hi) : "l"(v));
}
__device__ __forceinline__ unsigned smem_u32(const void* p) {
    return (unsigned)__cvta_generic_to_shared(p);
}
__device__ __forceinline__ void cpasync16(unsigned dst, const void* src) {
    asm volatile("cp.async.cg.shared.global [%0], [%1], 16;\n" :: "r"(dst), "l"(src));
}
#define CP_COMMIT() asm volatile("cp.async.commit_group;\n" ::: "memory")
#define CP_WAIT(n)  asm volatile("cp.async.wait_group %0;\n" :: "n"(n) : "memory")

// ---------------------------------------------------------------------------
// Kernel A: qp[dsp][b,c] = sum_{d in dsp-range(256)} query[b,d] * wq[d,c]
// Also zeroes d_out (256 blocks x 128 threads = 32768 floats exactly).
// ---------------------------------------------------------------------------
__global__ __launch_bounds__(128) void k_qproj(const float* __restrict__ query,
                                               const float* __restrict__ wq,
                                               float* __restrict__ out) {
    const int tx  = threadIdx.x;
    const int c0  = blockIdx.x * 128;
    const int b0  = blockIdx.y * 4;
    const int dsp = blockIdx.z;
    const int dr0 = dsp * 256;

    {
        int lin = blockIdx.x + 8 * blockIdx.y + 64 * blockIdx.z;
        out[lin * 128 + tx] = 0.0f;
    }

    __shared__ __align__(16) float sq[4][256];
#pragma unroll
    for (int i = 0; i < 2; i++) {
        int fl = i * 128 + tx;
        int bb = fl >> 6, d4 = fl & 63;
        *(float4*)&sq[bb][d4 * 4] =
            *(const float4*)(query + (size_t)(b0 + bb) * DD + dr0 + d4 * 4);
    }
    __syncthreads();

    u64 acc[4] = {0ull, 0ull, 0ull, 0ull};
    const float* wc = wq + (size_t)dr0 * DD + c0 + tx;
#pragma unroll 16
    for (int d = 0; d < 256; d += 2) {
        float w0 = wc[(size_t)d * DD];
        float w1 = wc[(size_t)(d + 1) * DD];
        u64 w2 = pack2(w0, w1);
#pragma unroll
        for (int bb = 0; bb < 4; bb++) {
            u64 q2 = *(const u64*)&sq[bb][d];
            fma2(acc[bb], q2, w2);
        }
    }
#pragma unroll
    for (int bb = 0; bb < 4; bb++) {
        float lo, hi; unpack2(acc[bb], lo, hi);
        g_qp[dsp][(size_t)(b0 + bb) * DD + c0 + tx] = lo + hi;
    }
}

// ---------------------------------------------------------------------------
// Kernel B: Ut[b,d,h] = (1/8) * sum_{c<64} wk[d, h*64+c] * q[b, h*64+c]
// ---------------------------------------------------------------------------
__global__ __launch_bounds__(128) void k_uproj(const float* __restrict__ wk) {
    const int tx = threadIdx.x;
    const int d0 = blockIdx.x * 128;
    const int h  = blockIdx.y;
    __shared__ __align__(16) float4 swk4[128 * 17];
    __shared__ __align__(16) float  sq[32][64];

#pragma unroll
    for (int i = 0; i < 16; i++) {
        int fl = i * 128 + tx;
        int r  = fl >> 4, c4 = fl & 15;
        swk4[r * 17 + c4] =
            *(const float4*)(wk + (size_t)(d0 + r) * DD + h * 64 + c4 * 4);
    }
#pragma unroll
    for (int i = 0; i < 4; i++) {
        int fl = i * 128 + tx;
        int bb = fl >> 4, c4 = fl & 15;
        float4 s = *(const float4*)(g_qp[0] + (size_t)bb * DD + h * 64 + c4 * 4);
#pragma unroll
        for (int p = 1; p < 4; p++) {
            float4 a = *(const float4*)(g_qp[p] + (size_t)bb * DD + h * 64 + c4 * 4);
            s.x += a.x; s.y += a.y; s.z += a.z; s.w += a.w;
        }
        *(float4*)&sq[bb][c4 * 4] = s;
    }
    __syncthreads();

    ulonglong2 wreg[16];
#pragma unroll
    for (int c4 = 0; c4 < 16; c4++)
        wreg[c4] = *(const ulonglong2*)&swk4[tx * 17 + c4];

    const int dst_base = (d0 + tx) * HH + h;
#pragma unroll 2
    for (int bb = 0; bb < 32; bb++) {
        u64 a2 = 0ull;
#pragma unroll
        for (int c4 = 0; c4 < 16; c4++) {
            ulonglong2 q2 = *(const ulonglong2*)&sq[bb][c4 * 4];
            fma2(a2, wreg[c4].x, q2.x);
            fma2(a2, wreg[c4].y, q2.y);
        }
        float lo, hi; unpack2(a2, lo, hi);
        g_Ut[(size_t)bb * (DD * HH) + dst_base] = (lo + hi) * 0.125f;
    }
}

// ---------------------------------------------------------------------------
// Kernel C: raw scores + per-warp-tile softmax stats.
// scores[b,h,n] = sum_d key[b,n,d] * Ut[b,d,h]   (streams key 512MB)
// 64-thr CTAs (2 warps); warp owns 128 n; thread owns 4 n.
// Epilogue: per head, warp-reduce (max, sumexp) over the 128-n tile
//           -> g_stat[(b*HH+h)*32 + tile].
// ---------------------------------------------------------------------------
__global__ __launch_bounds__(64, 5) void k_scores(const float* __restrict__ key) {
    const int tx   = threadIdx.x;
    const int w    = tx >> 5;
    const int l    = tx & 31;
    const int b    = blockIdx.y;
    const int n0   = blockIdx.x * 256;
    const int nwrp = n0 + w * 128;

    __shared__ __align__(16) float4 skW[2][2][128 * 5];
    __shared__ __align__(16) float4 sUW[2][2][64];

    const float* keyw = key + ((size_t)b * NN + nwrp) * DD;
    const float* Utb  = g_Ut + (size_t)b * (DD * HH);

    u64 acc[4][8];
#pragma unroll
    for (int n4 = 0; n4 < 4; n4++)
#pragma unroll
        for (int p = 0; p < 8; p++) acc[n4][p] = 0ull;

    {
#pragma unroll
        for (int i = 0; i < 16; i++) {
            int fl = i * 32 + l;
            int n = fl >> 2, q4 = fl & 3;
            cpasync16(smem_u32(&skW[w][0][n * 5 + q4]),
                      keyw + (size_t)n * DD + q4 * 4);
        }
#pragma unroll
        for (int j = 0; j < 2; j++)
            cpasync16(smem_u32(&sUW[w][0][j * 32 + l]), Utb + (j * 32 + l) * 4);
        CP_COMMIT();
    }

#pragma unroll 1
    for (int ch = 0; ch < 64; ch++) {
        if (ch + 1 < 64) {
            const int st = (ch + 1) & 1, d0 = (ch + 1) * 16;
#pragma unroll
            for (int i = 0; i < 16; i++) {
                int fl = i * 32 + l;
                int n = fl >> 2, q4 = fl & 3;
                cpasync16(smem_u32(&skW[w][st][n * 5 + q4]),
                          keyw + (size_t)n * DD + d0 + q4 * 4);
            }
#pragma unroll
            for (int j = 0; j < 2; j++)
                cpasync16(smem_u32(&sUW[w][st][j * 32 + l]),
                          Utb + d0 * HH + (j * 32 + l) * 4);
            CP_COMMIT();
            CP_WAIT(1);
        } else {
            CP_WAIT(0);
        }
        __syncwarp();

        const int st = ch & 1;
#pragma unroll
        for (int g = 0; g < 4; g++) {
            float4 kv[4];
#pragma unroll
            for (int n4 = 0; n4 < 4; n4++)
                kv[n4] = skW[w][st][(n4 * 32 + l) * 5 + g];
#pragma unroll
            for (int s = 0; s < 4; s++) {
                int dd = g * 4 + s;
                const ulonglong2* uv = (const ulonglong2*)&sUW[w][st][dd * 4];
                ulonglong2 u0 = uv[0], u1 = uv[1];
                ulonglong2 u2 = uv[2], u3 = uv[3];
#pragma unroll
                for (int n4 = 0; n4 < 4; n4++) {
                    float kvs = (s == 0) ? kv[n4].x : (s == 1) ? kv[n4].y
                              : (s == 2) ? kv[n4].z : kv[n4].w;
                    u64 kv2 = pack2(kvs, kvs);
                    fma2(acc[n4][0], u0.x, kv2);
                    fma2(acc[n4][1], u0.y, kv2);
                    fma2(acc[n4][2], u1.x, kv2);
                    fma2(acc[n4][3], u1.y, kv2);
                    fma2(acc[n4][4], u2.x, kv2);
                    fma2(acc[n4][5], u2.y, kv2);
                    fma2(acc[n4][6], u3.x, kv2);
                    fma2(acc[n4][7], u3.y, kv2);
                }
            }
        }
        __syncwarp();
    }

    // write raw scores
#pragma unroll
    for (int n4 = 0; n4 < 4; n4++) {
#pragma unroll
        for (int p = 0; p < 8; p++) {
            float lo, hi;
            unpack2(acc[n4][p], lo, hi);
            g_att[((size_t)b * HH + 2 * p)     * NN + nwrp + n4 * 32 + l] = lo;
            g_att[((size_t)b * HH + 2 * p + 1) * NN + nwrp + n4 * 32 + l] = hi;
        }
    }

    // epilogue: per-head (max, sumexp) over this warp's 128-n tile
    float mt[16];
#pragma unroll
    for (int h = 0; h < 16; h++) mt[h] = -3e38f;
#pragma unroll
    for (int n4 = 0; n4 < 4; n4++)
#pragma unroll
        for (int p = 0; p < 8; p++) {
            float lo, hi; unpack2(acc[n4][p], lo, hi);
            mt[2 * p]     = fmaxf(mt[2 * p], lo);
            mt[2 * p + 1] = fmaxf(mt[2 * p + 1], hi);
        }
#pragma unroll
    for (int h = 0; h < 16; h++)
#pragma unroll
        for (int o = 16; o; o >>= 1)
            mt[h] = fmaxf(mt[h], __shfl_xor_sync(0xffffffffu, mt[h], o));

    float st[16];
#pragma unroll
    for (int h = 0; h < 16; h++) st[h] = 0.f;
#pragma unroll
    for (int n4 = 0; n4 < 4; n4++)
#pragma unroll
        for (int p = 0; p < 8; p++) {
            float lo, hi; unpack2(acc[n4][p], lo, hi);
            st[2 * p]     += __expf(lo - mt[2 * p]);
            st[2 * p + 1] += __expf(hi - mt[2 * p + 1]);
        }
#pragma unroll
    for (int h = 0; h < 16; h++)
#pragma unroll
        for (int o = 16; o; o >>= 1)
            st[h] += __shfl_xor_sync(0xffffffffu, st[h], o);

    if (l == 0) {
        int wtile = blockIdx.x * 2 + w;
#pragma unroll
        for (int h = 0; h < 16; h++)
            g_stat[((size_t)b * HH + h) * 32 + wtile] = make_float2(mt[h], st[h]);
    }
}

// ---------------------------------------------------------------------------
// Kernel E: wp[seg][b,h,d] = sum_{n in seg(512)} softmax(att)[b,h,n]*value[b,n,d]
// Softmax applied during staging from tile stats (g_stat).
// grid (2 d-tiles of 512, 8 seg, 32 b), 128 thr; thread owns 4 consecutive d.
// 8-deep float4 register pipeline on value.
// ---------------------------------------------------------------------------
__global__ __launch_bounds__(128, 4) void k_wpart(const float* __restrict__ value) {
    const int tx  = threadIdx.x;
    const int d0  = blockIdx.x * 512;
    const int seg = blockIdx.y;
    const int b   = blockIdx.z;

    __shared__ __align__(16) float sA[512 * 20];   // [n][16h + 4 pad], 40KB
    __shared__ float2 sMS[16];                     // (m_glob, 1/s_glob) per head

    // global softmax stats from 32 tile-stats per row
    if (tx < 16) {
        const float2* gs = g_stat + ((size_t)b * HH + tx) * 32;
        float m = -3e38f;
#pragma unroll
        for (int t = 0; t < 32; t++) m = fmaxf(m, gs[t].x);
        float s = 0.f;
#pragma unroll
        for (int t = 0; t < 32; t++) {
            float2 p = gs[t];
            s += p.y * __expf(p.x - m);
        }
        sMS[tx] = make_float2(m, 1.f / s);
    }
    __syncthreads();

    const float* attb = g_att + (size_t)b * HH * NN + seg * 512;
#pragma unroll
    for (int i = 0; i < 16; i++) {
        int fl = i * 128 + tx;
        int h = fl >> 7, n4 = (fl & 127) * 4;
        float4 a = *(const float4*)(attb + (size_t)h * NN + n4);
        float2 ms = sMS[h];
        sA[(n4 + 0) * 20 + h] = __expf(a.x - ms.x) * ms.y;
        sA[(n4 + 1) * 20 + h] = __expf(a.y - ms.x) * ms.y;
        sA[(n4 + 2) * 20 + h] = __expf(a.z - ms.x) * ms.y;
        sA[(n4 + 3) * 20 + h] = __expf(a.w - ms.x) * ms.y;
    }
    __syncthreads();

    u64 acc[32];   // acc[dd*8+hp], dd in 0..3 (4 owned d), hp in 0..7
#pragma unroll
    for (int p = 0; p < 32; p++) acc[p] = 0ull;

    const float* valb = value + ((size_t)b * NN + seg * 512) * DD + d0 + tx * 4;

    float4 vc[8], vn[8];
#pragma unroll
    for (int j = 0; j < 8; j++)
        vc[j] = *(const float4*)(valb + (size_t)j * DD);

#pragma unroll 1
    for (int n = 0; n < 512; n += 8) {
        if (n + 8 < 512) {
#pragma unroll
            for (int j = 0; j < 8; j++)
                vn[j] = *(const float4*)(valb + (size_t)(n + 8 + j) * DD);
        }
#pragma unroll
        for (int j = 0; j < 8; j++) {
            float vs[4] = {vc[j].x, vc[j].y, vc[j].z, vc[j].w};
            const ulonglong2* av = (const ulonglong2*)&sA[(n + j) * 20];
            ulonglong2 a0 = av[0], a1 = av[1], a2 = av[2], a3 = av[3];
#pragma unroll
            for (int dd = 0; dd < 4; dd++) {
                u64 v2 = pack2(vs[dd], vs[dd]);
                fma2(acc[dd * 8 + 0], a0.x, v2);
                fma2(acc[dd * 8 + 1], a0.y, v2);
                fma2(acc[dd * 8 + 2], a1.x, v2);
                fma2(acc[dd * 8 + 3], a1.y, v2);
                fma2(acc[dd * 8 + 4], a2.x, v2);
                fma2(acc[dd * 8 + 5], a2.y, v2);
                fma2(acc[dd * 8 + 6], a3.x, v2);
                fma2(acc[dd * 8 + 7], a3.y, v2);
            }
        }
#pragma unroll
        for (int j = 0; j < 8; j++) vc[j] = vn[j];
    }

#pragma unroll
    for (int hp = 0; hp < 8; hp++) {
        float l0, h0x, l1, h1x, l2, h2x, l3, h3x;
        unpack2(acc[0 * 8 + hp], l0, h0x);
        unpack2(acc[1 * 8 + hp], l1, h1x);
        unpack2(acc[2 * 8 + hp], l2, h2x);
        unpack2(acc[3 * 8 + hp], l3, h3x);
        float4 olo = make_float4(l0, l1, l2, l3);
        float4 ohi = make_float4(h0x, h1x, h2x, h3x);
        *(float4*)(g_wp[seg] + ((size_t)b * HH + 2 * hp)     * DD + d0 + tx * 4) = olo;
        *(float4*)(g_wp[seg] + ((size_t)b * HH + 2 * hp + 1) * DD + d0 + tx * 4) = ohi;
    }
}

// ---------------------------------------------------------------------------
// Kernel F: out[b,c] += sum_{d in dsp-range(256)} w[b, c>>6, d] * wv[d, c]
// (w assembled on the fly from the 8 wpart partials)
// ---------------------------------------------------------------------------
__global__ __launch_bounds__(128) void k_oproj(const float* __restrict__ wv,
                                               float* __restrict__ out) {
    const int tx  = threadIdx.x;
    const int c0  = blockIdx.x * 128;
    const int b0  = blockIdx.y * 4;
    const int dsp = blockIdx.z;
    const int dr0 = dsp * 256;
    const int h0  = c0 >> 6;
    __shared__ __align__(16) float sw[4][2][256];

#pragma unroll
    for (int i = 0; i < 4; i++) {
        int fl = i * 128 + tx;
        int bb = fl >> 7, hh = (fl >> 6) & 1, d4 = fl & 63;
        size_t gidx = ((size_t)(b0 + bb) * HH + h0 + hh) * DD + dr0 + d4 * 4;
        float4 s = *(const float4*)(g_wp[0] + gidx);
#pragma unroll
        for (int p = 1; p < 8; p++) {
            float4 a = *(const float4*)(g_wp[p] + gidx);
            s.x += a.x; s.y += a.y; s.z += a.z; s.w += a.w;
        }
        *(float4*)&sw[bb][hh][d4 * 4] = s;
    }
    __syncthreads();

    const int hin = tx >> 6;
    u64 acc[4] = {0ull, 0ull, 0ull, 0ull};
    const float* wc = wv + (size_t)dr0 * DD + c0 + tx;
#pragma unroll 16
    for (int dd = 0; dd < 256; dd += 2) {
        float w0 = wc[(size_t)dd * DD];
        float w1 = wc[(size_t)(dd + 1) * DD];
        u64 w2 = pack2(w0, w1);
#pragma unroll
        for (int bb = 0; bb < 4; bb++) {
            u64 s2 = *(const u64*)&sw[bb][hin][dd];
            fma2(acc[bb], s2, w2);
        }
    }
#pragma unroll
    for (int bb = 0; bb < 4; bb++) {
        float lo, hi; unpack2(acc[bb], lo, hi);
        atomicAdd(&out[(size_t)(b0 + bb) * DD + c0 + tx], lo + hi);
    }
}

// ---------------------------------------------------------------------------
extern "C" void kernel_launch(void* const* d_in, const int* in_sizes, int n_in,
                              void* d_out, int out_size) {
    const float* query = (const float*)d_in[0];
    const float* key   = (const float*)d_in[1];
    const float* value = (const float*)d_in[2];
    const float* wq    = (const float*)d_in[3];
    const float* wk    = (const float*)d_in[4];
    const float* wv    = (const float*)d_in[5];
    float* out = (float*)d_out;

    k_qproj  <<<dim3(8, 8, 4),  128>>>(query, wq, out);
    k_uproj  <<<dim3(8, HH),    128>>>(wk);
    k_scores <<<dim3(16, BB),   64>>>(key);
    k_wpart  <<<dim3(2, 8, BB), 128>>>(value);   // 4th launch -> profiled
    k_oproj  <<<dim3(8, 8, 4),  128>>>(wv, out);
}

// round 10
// speedup vs baseline: 1.0225x; 1.0018x over previous
#include <cuda_runtime.h>

#define BB 32
#define NN 4096
#define DD 1024
#define HH 16

// Scratch (device globals)
__device__ float  g_qp[4][BB * DD];          // q projection partials over 4 d-ranges
__device__ float  g_Ut[BB * DD * HH];        // folded key vectors, transposed [b][d][h] (scaled 1/8)
__device__ float  g_att[BB * HH * NN];       // RAW scores
__device__ float2 g_stat[BB * HH * 32];      // per-(b,h,128n-tile) (max, sumexp)
__device__ float  g_wp[8][BB * HH * DD];     // partial attn@value over 8 n-segments

typedef unsigned long long u64;

__device__ __forceinline__ void fma2(u64 &d, u64 a, u64 b) {
    asm("fma.rn.f32x2 %0, %1, %2, %0;" : "+l"(d) : "l"(a), "l"(b));
}
__device__ __forceinline__ u64 pack2(float lo, float hi) {
    u64 r; asm("mov.b64 %0, {%1, %2};" : "=l"(r) : "f"(lo), "f"(hi)); return r;
}
__device__ __forceinline__ void unpack2(u64 v, float &lo, float &hi) {
    asm("mov.b64 {%0, %1}, %2;" : "=f"(lo), "=f"(hi) : "l"(v));
}
__device__ __forceinline__ unsigned smem_u32(const void* p) {
    return (unsigned)__cvta_generic_to_shared(p);
}
__device__ __forceinline__ void cpasync16(unsigned dst, const void* src) {
    asm volatile("cp.async.cg.shared.global [%0], [%1], 16;\n" :: "r"(dst), "l"(src));
}
#define CP_COMMIT() asm volatile("cp.async.commit_group;\n" ::: "memory")
#define CP_WAIT(n)  asm volatile("cp.async.wait_group %0;\n" :: "n"(n) : "memory")

// ---------------------------------------------------------------------------
// Kernel A: qp[dsp][b,c] = sum_{d in dsp-range(256)} query[b,d] * wq[d,c]
// Also zeroes d_out (256 blocks x 128 threads = 32768 floats exactly).
// ---------------------------------------------------------------------------
__global__ __launch_bounds__(128) void k_qproj(const float* __restrict__ query,
                                               const float* __restrict__ wq,
                                               float* __restrict__ out) {
    const int tx  = threadIdx.x;
    const int c0  = blockIdx.x * 128;
    const int b0  = blockIdx.y * 4;
    const int dsp = blockIdx.z;
    const int dr0 = dsp * 256;

    {
        int lin = blockIdx.x + 8 * blockIdx.y + 64 * blockIdx.z;
        out[lin * 128 + tx] = 0.0f;
    }

    __shared__ __align__(16) float sq[4][256];
#pragma unroll
    for (int i = 0; i < 2; i++) {
        int fl = i * 128 + tx;
        int bb = fl >> 6, d4 = fl & 63;
        *(float4*)&sq[bb][d4 * 4] =
            *(const float4*)(query + (size_t)(b0 + bb) * DD + dr0 + d4 * 4);
    }
    __syncthreads();

    u64 acc[4] = {0ull, 0ull, 0ull, 0ull};
    const float* wc = wq + (size_t)dr0 * DD + c0 + tx;
#pragma unroll 16
    for (int d = 0; d < 256; d += 2) {
        float w0 = wc[(size_t)d * DD];
        float w1 = wc[(size_t)(d + 1) * DD];
        u64 w2 = pack2(w0, w1);
#pragma unroll
        for (int bb = 0; bb < 4; bb++) {
            u64 q2 = *(const u64*)&sq[bb][d];
            fma2(acc[bb], q2, w2);
        }
    }
#pragma unroll
    for (int bb = 0; bb < 4; bb++) {
        float lo, hi; unpack2(acc[bb], lo, hi);
        g_qp[dsp][(size_t)(b0 + bb) * DD + c0 + tx] = lo + hi;
    }
}

// ---------------------------------------------------------------------------
// Kernel B: Ut[b,d,h] = (1/8) * sum_{c<64} wk[d, h*64+c] * q[b, h*64+c]
// ---------------------------------------------------------------------------
__global__ __launch_bounds__(128) void k_uproj(const float* __restrict__ wk) {
    const int tx = threadIdx.x;
    const int d0 = blockIdx.x * 128;
    const int h  = blockIdx.y;
    __shared__ __align__(16) float4 swk4[128 * 17];
    __shared__ __align__(16) float  sq[32][64];

#pragma unroll
    for (int i = 0; i < 16; i++) {
        int fl = i * 128 + tx;
        int r  = fl >> 4, c4 = fl & 15;
        swk4[r * 17 + c4] =
            *(const float4*)(wk + (size_t)(d0 + r) * DD + h * 64 + c4 * 4);
    }
#pragma unroll
    for (int i = 0; i < 4; i++) {
        int fl = i * 128 + tx;
        int bb = fl >> 4, c4 = fl & 15;
        float4 s = *(const float4*)(g_qp[0] + (size_t)bb * DD + h * 64 + c4 * 4);
#pragma unroll
        for (int p = 1; p < 4; p++) {
            float4 a = *(const float4*)(g_qp[p] + (size_t)bb * DD + h * 64 + c4 * 4);
            s.x += a.x; s.y += a.y; s.z += a.z; s.w += a.w;
        }
        *(float4*)&sq[bb][c4 * 4] = s;
    }
    __syncthreads();

    ulonglong2 wreg[16];
#pragma unroll
    for (int c4 = 0; c4 < 16; c4++)
        wreg[c4] = *(const ulonglong2*)&swk4[tx * 17 + c4];

    const int dst_base = (d0 + tx) * HH + h;
#pragma unroll 2
    for (int bb = 0; bb < 32; bb++) {
        u64 a2 = 0ull;
#pragma unroll
        for (int c4 = 0; c4 < 16; c4++) {
            ulonglong2 q2 = *(const ulonglong2*)&sq[bb][c4 * 4];
            fma2(a2, wreg[c4].x, q2.x);
            fma2(a2, wreg[c4].y, q2.y);
        }
        float lo, hi; unpack2(a2, lo, hi);
        g_Ut[(size_t)bb * (DD * HH) + dst_base] = (lo + hi) * 0.125f;
    }
}

// ---------------------------------------------------------------------------
// Kernel C: raw scores + per-warp-tile softmax stats.
// scores[b,h,n] = sum_d key[b,n,d] * Ut[b,d,h]   (streams key 512MB)
// 64-thr CTAs (2 warps); warp owns 128 n; thread owns 4 n.
// Epilogue: per head, warp-reduce (max, sumexp) over the 128-n tile
//           -> g_stat[(b*HH+h)*32 + tile].
// ---------------------------------------------------------------------------
__global__ __launch_bounds__(64, 5) void k_scores(const float* __restrict__ key) {
    const int tx   = threadIdx.x;
    const int w    = tx >> 5;
    const int l    = tx & 31;
    const int b    = blockIdx.y;
    const int n0   = blockIdx.x * 256;
    const int nwrp = n0 + w * 128;

    __shared__ __align__(16) float4 skW[2][2][128 * 5];
    __shared__ __align__(16) float4 sUW[2][2][64];

    const float* keyw = key + ((size_t)b * NN + nwrp) * DD;
    const float* Utb  = g_Ut + (size_t)b * (DD * HH);

    u64 acc[4][8];
#pragma unroll
    for (int n4 = 0; n4 < 4; n4++)
#pragma unroll
        for (int p = 0; p < 8; p++) acc[n4][p] = 0ull;

    {
#pragma unroll
        for (int i = 0; i < 16; i++) {
            int fl = i * 32 + l;
            int n = fl >> 2, q4 = fl & 3;
            cpasync16(smem_u32(&skW[w][0][n * 5 + q4]),
                      keyw + (size_t)n * DD + q4 * 4);
        }
#pragma unroll
        for (int j = 0; j < 2; j++)
            cpasync16(smem_u32(&sUW[w][0][j * 32 + l]), Utb + (j * 32 + l) * 4);
        CP_COMMIT();
    }

#pragma unroll 1
    for (int ch = 0; ch < 64; ch++) {
        if (ch + 1 < 64) {
            const int st = (ch + 1) & 1, d0 = (ch + 1) * 16;
#pragma unroll
            for (int i = 0; i < 16; i++) {
                int fl = i * 32 + l;
                int n = fl >> 2, q4 = fl & 3;
                cpasync16(smem_u32(&skW[w][st][n * 5 + q4]),
                          keyw + (size_t)n * DD + d0 + q4 * 4);
            }
#pragma unroll
            for (int j = 0; j < 2; j++)
                cpasync16(smem_u32(&sUW[w][st][j * 32 + l]),
                          Utb + d0 * HH + (j * 32 + l) * 4);
            CP_COMMIT();
            CP_WAIT(1);
        } else {
            CP_WAIT(0);
        }
        __syncwarp();

        const int st = ch & 1;
#pragma unroll
        for (int g = 0; g < 4; g++) {
            float4 kv[4];
#pragma unroll
            for (int n4 = 0; n4 < 4; n4++)
                kv[n4] = skW[w][st][(n4 * 32 + l) * 5 + g];
#pragma unroll
            for (int s = 0; s < 4; s++) {
                int dd = g * 4 + s;
                const ulonglong2* uv = (const ulonglong2*)&sUW[w][st][dd * 4];
                ulonglong2 u0 = uv[0], u1 = uv[1];
                ulonglong2 u2 = uv[2], u3 = uv[3];
#pragma unroll
                for (int n4 = 0; n4 < 4; n4++) {
                    float kvs = (s == 0) ? kv[n4].x : (s == 1) ? kv[n4].y
                              : (s == 2) ? kv[n4].z : kv[n4].w;
                    u64 kv2 = pack2(kvs, kvs);
                    fma2(acc[n4][0], u0.x, kv2);
                    fma2(acc[n4][1], u0.y, kv2);
                    fma2(acc[n4][2], u1.x, kv2);
                    fma2(acc[n4][3], u1.y, kv2);
                    fma2(acc[n4][4], u2.x, kv2);
                    fma2(acc[n4][5], u2.y, kv2);
                    fma2(acc[n4][6], u3.x, kv2);
                    fma2(acc[n4][7], u3.y, kv2);
                }
            }
        }
        __syncwarp();
    }

    // write raw scores
#pragma unroll
    for (int n4 = 0; n4 < 4; n4++) {
#pragma unroll
        for (int p = 0; p < 8; p++) {
            float lo, hi;
            unpack2(acc[n4][p], lo, hi);
            g_att[((size_t)b * HH + 2 * p)     * NN + nwrp + n4 * 32 + l] = lo;
            g_att[((size_t)b * HH + 2 * p + 1) * NN + nwrp + n4 * 32 + l] = hi;
        }
    }

    // epilogue: per-head (max, sumexp) over this warp's 128-n tile
    float mt[16];
#pragma unroll
    for (int h = 0; h < 16; h++) mt[h] = -3e38f;
#pragma unroll
    for (int n4 = 0; n4 < 4; n4++)
#pragma unroll
        for (int p = 0; p < 8; p++) {
            float lo, hi; unpack2(acc[n4][p], lo, hi);
            mt[2 * p]     = fmaxf(mt[2 * p], lo);
            mt[2 * p + 1] = fmaxf(mt[2 * p + 1], hi);
        }
#pragma unroll
    for (int h = 0; h < 16; h++)
#pragma unroll
        for (int o = 16; o; o >>= 1)
            mt[h] = fmaxf(mt[h], __shfl_xor_sync(0xffffffffu, mt[h], o));

    float st[16];
#pragma unroll
    for (int h = 0; h < 16; h++) st[h] = 0.f;
#pragma unroll
    for (int n4 = 0; n4 < 4; n4++)
#pragma unroll
        for (int p = 0; p < 8; p++) {
            float lo, hi; unpack2(acc[n4][p], lo, hi);
            st[2 * p]     += __expf(lo - mt[2 * p]);
            st[2 * p + 1] += __expf(hi - mt[2 * p + 1]);
        }
#pragma unroll
    for (int h = 0; h < 16; h++)
#pragma unroll
        for (int o = 16; o; o >>= 1)
            st[h] += __shfl_xor_sync(0xffffffffu, st[h], o);

    if (l == 0) {
        int wtile = blockIdx.x * 2 + w;
#pragma unroll
        for (int h = 0; h < 16; h++)
            g_stat[((size_t)b * HH + h) * 32 + wtile] = make_float2(mt[h], st[h]);
    }
}

// ---------------------------------------------------------------------------
// Kernel E: wp[seg][b,h,d] = sum_{n in seg(512)} softmax(att)[b,h,n]*value[b,n,d]
// Softmax applied during staging from tile stats (g_stat).
// grid (2 d-tiles of 512, 8 seg, 32 b), 128 thr; thread owns 4 consecutive d.
// 8-deep float4 register pipeline on value.
// ---------------------------------------------------------------------------
__global__ __launch_bounds__(128, 4) void k_wpart(const float* __restrict__ value) {
    const int tx  = threadIdx.x;
    const int d0  = blockIdx.x * 512;
    const int seg = blockIdx.y;
    const int b   = blockIdx.z;

    __shared__ __align__(16) float sA[512 * 20];   // [n][16h + 4 pad], 40KB
    __shared__ float2 sMS[16];                     // (m_glob, 1/s_glob) per head

    // global softmax stats from 32 tile-stats per row
    if (tx < 16) {
        const float2* gs = g_stat + ((size_t)b * HH + tx) * 32;
        float m = -3e38f;
#pragma unroll
        for (int t = 0; t < 32; t++) m = fmaxf(m, gs[t].x);
        float s = 0.f;
#pragma unroll
        for (int t = 0; t < 32; t++) {
            float2 p = gs[t];
            s += p.y * __expf(p.x - m);
        }
        sMS[tx] = make_float2(m, 1.f / s);
    }
    __syncthreads();

    const float* attb = g_att + (size_t)b * HH * NN + seg * 512;
#pragma unroll
    for (int i = 0; i < 16; i++) {
        int fl = i * 128 + tx;
        int h = fl >> 7, n4 = (fl & 127) * 4;
        float4 a = *(const float4*)(attb + (size_t)h * NN + n4);
        float2 ms = sMS[h];
        sA[(n4 + 0) * 20 + h] = __expf(a.x - ms.x) * ms.y;
        sA[(n4 + 1) * 20 + h] = __expf(a.y - ms.x) * ms.y;
        sA[(n4 + 2) * 20 + h] = __expf(a.z - ms.x) * ms.y;
        sA[(n4 + 3) * 20 + h] = __expf(a.w - ms.x) * ms.y;
    }
    __syncthreads();

    u64 acc[32];   // acc[dd*8+hp], dd in 0..3 (4 owned d), hp in 0..7
#pragma unroll
    for (int p = 0; p < 32; p++) acc[p] = 0ull;

    const float* valb = value + ((size_t)b * NN + seg * 512) * DD + d0 + tx * 4;

    float4 vc[8], vn[8];
#pragma unroll
    for (int j = 0; j < 8; j++)
        vc[j] = *(const float4*)(valb + (size_t)j * DD);

#pragma unroll 1
    for (int n = 0; n < 512; n += 8) {
        if (n + 8 < 512) {
#pragma unroll
            for (int j = 0; j < 8; j++)
                vn[j] = *(const float4*)(valb + (size_t)(n + 8 + j) * DD);
        }
#pragma unroll
        for (int j = 0; j < 8; j++) {
            float vs[4] = {vc[j].x, vc[j].y, vc[j].z, vc[j].w};
            const ulonglong2* av = (const ulonglong2*)&sA[(n + j) * 20];
            ulonglong2 a0 = av[0], a1 = av[1], a2 = av[2], a3 = av[3];
#pragma unroll
            for (int dd = 0; dd < 4; dd++) {
                u64 v2 = pack2(vs[dd], vs[dd]);
                fma2(acc[dd * 8 + 0], a0.x, v2);
                fma2(acc[dd * 8 + 1], a0.y, v2);
                fma2(acc[dd * 8 + 2], a1.x, v2);
                fma2(acc[dd * 8 + 3], a1.y, v2);
                fma2(acc[dd * 8 + 4], a2.x, v2);
                fma2(acc[dd * 8 + 5], a2.y, v2);
                fma2(acc[dd * 8 + 6], a3.x, v2);
                fma2(acc[dd * 8 + 7], a3.y, v2);
            }
        }
#pragma unroll
        for (int j = 0; j < 8; j++) vc[j] = vn[j];
    }

#pragma unroll
    for (int hp = 0; hp < 8; hp++) {
        float l0, h0x, l1, h1x, l2, h2x, l3, h3x;
        unpack2(acc[0 * 8 + hp], l0, h0x);
        unpack2(acc[1 * 8 + hp], l1, h1x);
        unpack2(acc[2 * 8 + hp], l2, h2x);
        unpack2(acc[3 * 8 + hp], l3, h3x);
        float4 olo = make_float4(l0, l1, l2, l3);
        float4 ohi = make_float4(h0x, h1x, h2x, h3x);
        *(float4*)(g_wp[seg] + ((size_t)b * HH + 2 * hp)     * DD + d0 + tx * 4) = olo;
        *(float4*)(g_wp[seg] + ((size_t)b * HH + 2 * hp + 1) * DD + d0 + tx * 4) = ohi;
    }
}

// ---------------------------------------------------------------------------
// Kernel F: out[b,c] += sum_{d in dsp-range(256)} w[b, c>>6, d] * wv[d, c]
// (w assembled on the fly from the 8 wpart partials)
// ---------------------------------------------------------------------------
__global__ __launch_bounds__(128) void k_oproj(const float* __restrict__ wv,
                                               float* __restrict__ out) {
    const int tx  = threadIdx.x;
    const int c0  = blockIdx.x * 128;
    const int b0  = blockIdx.y * 4;
    const int dsp = blockIdx.z;
    const int dr0 = dsp * 256;
    const int h0  = c0 >> 6;
    __shared__ __align__(16) float sw[4][2][256];

#pragma unroll
    for (int i = 0; i < 4; i++) {
        int fl = i * 128 + tx;
        int bb = fl >> 7, hh = (fl >> 6) & 1, d4 = fl & 63;
        size_t gidx = ((size_t)(b0 + bb) * HH + h0 + hh) * DD + dr0 + d4 * 4;
        float4 s = *(const float4*)(g_wp[0] + gidx);
#pragma unroll
        for (int p = 1; p < 8; p++) {
            float4 a = *(const float4*)(g_wp[p] + gidx);
            s.x += a.x; s.y += a.y; s.z += a.z; s.w += a.w;
        }
        *(float4*)&sw[bb][hh][d4 * 4] = s;
    }
    __syncthreads();

    const int hin = tx >> 6;
    u64 acc[4] = {0ull, 0ull, 0ull, 0ull};
    const float* wc = wv + (size_t)dr0 * DD + c0 + tx;
#pragma unroll 16
    for (int dd = 0; dd < 256; dd += 2) {
        float w0 = wc[(size_t)dd * DD];
        float w1 = wc[(size_t)(dd + 1) * DD];
        u64 w2 = pack2(w0, w1);
#pragma unroll
        for (int bb = 0; bb < 4; bb++) {
            u64 s2 = *(const u64*)&sw[bb][hin][dd];
            fma2(acc[bb], s2, w2);
        }
    }
#pragma unroll
    for (int bb = 0; bb < 4; bb++) {
        float lo, hi; unpack2(acc[bb], lo, hi);
        atomicAdd(&out[(size_t)(b0 + bb) * DD + c0 + tx], lo + hi);
    }
}

// ---------------------------------------------------------------------------
extern "C" void kernel_launch(void* const* d_in, const int* in_sizes, int n_in,
                              void* d_out, int out_size) {
    const float* query = (const float*)d_in[0];
    const float* key   = (const float*)d_in[1];
    const float* value = (const float*)d_in[2];
    const float* wq    = (const float*)d_in[3];
    const float* wk    = (const float*)d_in[4];
    const float* wv    = (const float*)d_in[5];
    float* out = (float*)d_out;

    k_qproj  <<<dim3(8, 8, 4),  128>>>(query, wq, out);
    k_uproj  <<<dim3(8, HH),    128>>>(wk);
    k_scores <<<dim3(16, BB),   64>>>(key);
    k_wpart  <<<dim3(2, 8, BB), 128>>>(value);   // 4th launch -> profiled
    k_oproj  <<<dim3(8, 8, 4),  128>>>(wv, out);
}

// round 11
// speedup vs baseline: 1.3254x; 1.2963x over previous
#include <cuda_runtime.h>

#define BB 32
#define NN 4096
#define DD 1024
#define HH 16

// Scratch (device globals)
__device__ float  g_qp[4][BB * DD];          // q projection partials over 4 d-ranges
__device__ float  g_Ut[BB * DD * HH];        // folded key vectors, transposed [b][d][h] (scaled 1/8)
__device__ float  g_att[BB * HH * NN];       // RAW scores
__device__ float2 g_stat[BB * HH * 32];      // per-(b,h,128n-tile) (max, sumexp)
__device__ float  g_wp[8][BB * HH * DD];     // partial attn@value over 8 n-segments

typedef unsigned long long u64;

__device__ __forceinline__ void fma2(u64 &d, u64 a, u64 b) {
    asm("fma.rn.f32x2 %0, %1, %2, %0;" : "+l"(d) : "l"(a), "l"(b));
}
__device__ __forceinline__ u64 pack2(float lo, float hi) {
    u64 r; asm("mov.b64 %0, {%1, %2};" : "=l"(r) : "f"(lo), "f"(hi)); return r;
}
__device__ __forceinline__ void unpack2(u64 v, float &lo, float &hi) {
    asm("mov.b64 {%0, %1}, %2;" : "=f"(lo), "=f"(hi) : "l"(v));
}
__device__ __forceinline__ unsigned smem_u32(const void* p) {
    return (unsigned)__cvta_generic_to_shared(p);
}
__device__ __forceinline__ void cpasync16(unsigned dst, const void* src) {
    asm volatile("cp.async.cg.shared.global [%0], [%1], 16;\n" :: "r"(dst), "l"(src));
}
#define CP_COMMIT() asm volatile("cp.async.commit_group;\n" ::: "memory")
#define CP_WAIT(n)  asm volatile("cp.async.wait_group %0;\n" :: "n"(n) : "memory")

// ---------------------------------------------------------------------------
// Kernel A: qp[dsp][b,c] = sum_{d in dsp-range(256)} query[b,d] * wq[d,c]
// Also zeroes d_out (256 blocks x 128 threads = 32768 floats exactly).
// ---------------------------------------------------------------------------
__global__ __launch_bounds__(128) void k_qproj(const float* __restrict__ query,
                                               const float* __restrict__ wq,
                                               float* __restrict__ out) {
    const int tx  = threadIdx.x;
    const int c0  = blockIdx.x * 128;
    const int b0  = blockIdx.y * 4;
    const int dsp = blockIdx.z;
    const int dr0 = dsp * 256;

    {
        int lin = blockIdx.x + 8 * blockIdx.y + 64 * blockIdx.z;
        out[lin * 128 + tx] = 0.0f;
    }

    __shared__ __align__(16) float sq[4][256];
#pragma unroll
    for (int i = 0; i < 2; i++) {
        int fl = i * 128 + tx;
        int bb = fl >> 6, d4 = fl & 63;
        *(float4*)&sq[bb][d4 * 4] =
            *(const float4*)(query + (size_t)(b0 + bb) * DD + dr0 + d4 * 4);
    }
    __syncthreads();

    u64 acc[4] = {0ull, 0ull, 0ull, 0ull};
    const float* wc = wq + (size_t)dr0 * DD + c0 + tx;
#pragma unroll 16
    for (int d = 0; d < 256; d += 2) {
        float w0 = wc[(size_t)d * DD];
        float w1 = wc[(size_t)(d + 1) * DD];
        u64 w2 = pack2(w0, w1);
#pragma unroll
        for (int bb = 0; bb < 4; bb++) {
            u64 q2 = *(const u64*)&sq[bb][d];
            fma2(acc[bb], q2, w2);
        }
    }
#pragma unroll
    for (int bb = 0; bb < 4; bb++) {
        float lo, hi; unpack2(acc[bb], lo, hi);
        g_qp[dsp][(size_t)(b0 + bb) * DD + c0 + tx] = lo + hi;
    }
}

// ---------------------------------------------------------------------------
// Kernel B: Ut[b,d,h] = (1/8) * sum_{c<64} wk[d, h*64+c] * q[b, h*64+c]
// ---------------------------------------------------------------------------
__global__ __launch_bounds__(128) void k_uproj(const float* __restrict__ wk) {
    const int tx = threadIdx.x;
    const int d0 = blockIdx.x * 128;
    const int h  = blockIdx.y;
    __shared__ __align__(16) float4 swk4[128 * 17];
    __shared__ __align__(16) float  sq[32][64];

#pragma unroll
    for (int i = 0; i < 16; i++) {
        int fl = i * 128 + tx;
        int r  = fl >> 4, c4 = fl & 15;
        swk4[r * 17 + c4] =
            *(const float4*)(wk + (size_t)(d0 + r) * DD + h * 64 + c4 * 4);
    }
#pragma unroll
    for (int i = 0; i < 4; i++) {
        int fl = i * 128 + tx;
        int bb = fl >> 4, c4 = fl & 15;
        float4 s = *(const float4*)(g_qp[0] + (size_t)bb * DD + h * 64 + c4 * 4);
#pragma unroll
        for (int p = 1; p < 4; p++) {
            float4 a = *(const float4*)(g_qp[p] + (size_t)bb * DD + h * 64 + c4 * 4);
            s.x += a.x; s.y += a.y; s.z += a.z; s.w += a.w;
        }
        *(float4*)&sq[bb][c4 * 4] = s;
    }
    __syncthreads();

    ulonglong2 wreg[16];
#pragma unroll
    for (int c4 = 0; c4 < 16; c4++)
        wreg[c4] = *(const ulonglong2*)&swk4[tx * 17 + c4];

    const int dst_base = (d0 + tx) * HH + h;
#pragma unroll 2
    for (int bb = 0; bb < 32; bb++) {
        u64 a2 = 0ull;
#pragma unroll
        for (int c4 = 0; c4 < 16; c4++) {
            ulonglong2 q2 = *(const ulonglong2*)&sq[bb][c4 * 4];
            fma2(a2, wreg[c4].x, q2.x);
            fma2(a2, wreg[c4].y, q2.y);
        }
        float lo, hi; unpack2(a2, lo, hi);
        g_Ut[(size_t)bb * (DD * HH) + dst_base] = (lo + hi) * 0.125f;
    }
}

// ---------------------------------------------------------------------------
// Kernel C: raw scores + per-warp-tile softmax stats. (R10, unchanged)
// ---------------------------------------------------------------------------
__global__ __launch_bounds__(64, 5) void k_scores(const float* __restrict__ key) {
    const int tx   = threadIdx.x;
    const int w    = tx >> 5;
    const int l    = tx & 31;
    const int b    = blockIdx.y;
    const int n0   = blockIdx.x * 256;
    const int nwrp = n0 + w * 128;

    __shared__ __align__(16) float4 skW[2][2][128 * 5];
    __shared__ __align__(16) float4 sUW[2][2][64];

    const float* keyw = key + ((size_t)b * NN + nwrp) * DD;
    const float* Utb  = g_Ut + (size_t)b * (DD * HH);

    u64 acc[4][8];
#pragma unroll
    for (int n4 = 0; n4 < 4; n4++)
#pragma unroll
        for (int p = 0; p < 8; p++) acc[n4][p] = 0ull;

    {
#pragma unroll
        for (int i = 0; i < 16; i++) {
            int fl = i * 32 + l;
            int n = fl >> 2, q4 = fl & 3;
            cpasync16(smem_u32(&skW[w][0][n * 5 + q4]),
                      keyw + (size_t)n * DD + q4 * 4);
        }
#pragma unroll
        for (int j = 0; j < 2; j++)
            cpasync16(smem_u32(&sUW[w][0][j * 32 + l]), Utb + (j * 32 + l) * 4);
        CP_COMMIT();
    }

#pragma unroll 1
    for (int ch = 0; ch < 64; ch++) {
        if (ch + 1 < 64) {
            const int st = (ch + 1) & 1, d0 = (ch + 1) * 16;
#pragma unroll
            for (int i = 0; i < 16; i++) {
                int fl = i * 32 + l;
                int n = fl >> 2, q4 = fl & 3;
                cpasync16(smem_u32(&skW[w][st][n * 5 + q4]),
                          keyw + (size_t)n * DD + d0 + q4 * 4);
            }
#pragma unroll
            for (int j = 0; j < 2; j++)
                cpasync16(smem_u32(&sUW[w][st][j * 32 + l]),
                          Utb + d0 * HH + (j * 32 + l) * 4);
            CP_COMMIT();
            CP_WAIT(1);
        } else {
            CP_WAIT(0);
        }
        __syncwarp();

        const int st = ch & 1;
#pragma unroll
        for (int g = 0; g < 4; g++) {
            float4 kv[4];
#pragma unroll
            for (int n4 = 0; n4 < 4; n4++)
                kv[n4] = skW[w][st][(n4 * 32 + l) * 5 + g];
#pragma unroll
            for (int s = 0; s < 4; s++) {
                int dd = g * 4 + s;
                const ulonglong2* uv = (const ulonglong2*)&sUW[w][st][dd * 4];
                ulonglong2 u0 = uv[0], u1 = uv[1];
                ulonglong2 u2 = uv[2], u3 = uv[3];
#pragma unroll
                for (int n4 = 0; n4 < 4; n4++) {
                    float kvs = (s == 0) ? kv[n4].x : (s == 1) ? kv[n4].y
                              : (s == 2) ? kv[n4].z : kv[n4].w;
                    u64 kv2 = pack2(kvs, kvs);
                    fma2(acc[n4][0], u0.x, kv2);
                    fma2(acc[n4][1], u0.y, kv2);
                    fma2(acc[n4][2], u1.x, kv2);
                    fma2(acc[n4][3], u1.y, kv2);
                    fma2(acc[n4][4], u2.x, kv2);
                    fma2(acc[n4][5], u2.y, kv2);
                    fma2(acc[n4][6], u3.x, kv2);
                    fma2(acc[n4][7], u3.y, kv2);
                }
            }
        }
        __syncwarp();
    }

#pragma unroll
    for (int n4 = 0; n4 < 4; n4++) {
#pragma unroll
        for (int p = 0; p < 8; p++) {
            float lo, hi;
            unpack2(acc[n4][p], lo, hi);
            g_att[((size_t)b * HH + 2 * p)     * NN + nwrp + n4 * 32 + l] = lo;
            g_att[((size_t)b * HH + 2 * p + 1) * NN + nwrp + n4 * 32 + l] = hi;
        }
    }

    float mt[16];
#pragma unroll
    for (int h = 0; h < 16; h++) mt[h] = -3e38f;
#pragma unroll
    for (int n4 = 0; n4 < 4; n4++)
#pragma unroll
        for (int p = 0; p < 8; p++) {
            float lo, hi; unpack2(acc[n4][p], lo, hi);
            mt[2 * p]     = fmaxf(mt[2 * p], lo);
            mt[2 * p + 1] = fmaxf(mt[2 * p + 1], hi);
        }
#pragma unroll
    for (int h = 0; h < 16; h++)
#pragma unroll
        for (int o = 16; o; o >>= 1)
            mt[h] = fmaxf(mt[h], __shfl_xor_sync(0xffffffffu, mt[h], o));

    float st[16];
#pragma unroll
    for (int h = 0; h < 16; h++) st[h] = 0.f;
#pragma unroll
    for (int n4 = 0; n4 < 4; n4++)
#pragma unroll
        for (int p = 0; p < 8; p++) {
            float lo, hi; unpack2(acc[n4][p], lo, hi);
            st[2 * p]     += __expf(lo - mt[2 * p]);
            st[2 * p + 1] += __expf(hi - mt[2 * p + 1]);
        }
#pragma unroll
    for (int h = 0; h < 16; h++)
#pragma unroll
        for (int o = 16; o; o >>= 1)
            st[h] += __shfl_xor_sync(0xffffffffu, st[h], o);

    if (l == 0) {
        int wtile = blockIdx.x * 2 + w;
#pragma unroll
        for (int h = 0; h < 16; h++)
            g_stat[((size_t)b * HH + h) * 32 + wtile] = make_float2(mt[h], st[h]);
    }
}

// ---------------------------------------------------------------------------
// Kernel E (v3): wp[seg][b,h,d] = sum_{n in seg(512)} attn[b,h,n]*value[b,n,d]
// Softmax applied during att staging from tile stats.
// VALUE VIA cp.async DOUBLE BUFFER (8n x 512d = 16KB/stage). Each thread
// copies & consumes only its own smem words -> NO barriers in the mainloop.
// Thread owns 4 consecutive d; acc[dd][hp] = 32 u64 f32x2 (head pairs).
// ---------------------------------------------------------------------------
__global__ __launch_bounds__(128, 3) void k_wpart(const float* __restrict__ value) {
    const int tx  = threadIdx.x;
    const int d0  = blockIdx.x * 512;
    const int seg = blockIdx.y;
    const int b   = blockIdx.z;

    __shared__ __align__(16) float  sA[512 * 20];    // [n][16h + 4 pad], 40KB
    __shared__ __align__(16) float4 sV[2][8][128];   // 2 stages x 8n x 512d, 32KB
    __shared__ float2 sMS[16];                       // (m_glob, 1/s_glob) per head

    // global softmax stats from the 32 per-tile stats of each row
    if (tx < 16) {
        const float2* gs = g_stat + ((size_t)b * HH + tx) * 32;
        float m = -3e38f;
#pragma unroll
        for (int t = 0; t < 32; t++) m = fmaxf(m, gs[t].x);
        float s = 0.f;
#pragma unroll
        for (int t = 0; t < 32; t++) {
            float2 p = gs[t];
            s += p.y * __expf(p.x - m);
        }
        sMS[tx] = make_float2(m, 1.f / s);
    }

    const float* valb = value + ((size_t)b * NN + seg * 512) * DD + d0 + tx * 4;

    // prologue: stage value chunk 0 (no dependency on sA/sMS)
#pragma unroll
    for (int j = 0; j < 8; j++)
        cpasync16(smem_u32(&sV[0][j][tx]), valb + (size_t)j * DD);
    CP_COMMIT();

    __syncthreads();   // sMS ready

    const float* attb = g_att + (size_t)b * HH * NN + seg * 512;
#pragma unroll
    for (int i = 0; i < 16; i++) {
        int fl = i * 128 + tx;
        int h = fl >> 7, n4 = (fl & 127) * 4;
        float4 a = *(const float4*)(attb + (size_t)h * NN + n4);
        float2 ms = sMS[h];
        sA[(n4 + 0) * 20 + h] = __expf(a.x - ms.x) * ms.y;
        sA[(n4 + 1) * 20 + h] = __expf(a.y - ms.x) * ms.y;
        sA[(n4 + 2) * 20 + h] = __expf(a.z - ms.x) * ms.y;
        sA[(n4 + 3) * 20 + h] = __expf(a.w - ms.x) * ms.y;
    }
    __syncthreads();

    u64 acc[32];   // acc[dd*8+hp], dd in 0..3 (owned d), hp in 0..7 (head pair)
#pragma unroll
    for (int p = 0; p < 32; p++) acc[p] = 0ull;

#pragma unroll 1
    for (int ch = 0; ch < 64; ch++) {
        if (ch + 1 < 64) {
            const int st = (ch + 1) & 1;
            const float* src = valb + (size_t)(ch + 1) * 8 * DD;
#pragma unroll
            for (int j = 0; j < 8; j++)
                cpasync16(smem_u32(&sV[st][j][tx]), src + (size_t)j * DD);
            CP_COMMIT();
            CP_WAIT(1);
        } else {
            CP_WAIT(0);
        }
        // no barrier: this thread reads only the words it copied itself

        const int st = ch & 1;
        const float* sArow = &sA[ch * 8 * 20];
#pragma unroll
        for (int j = 0; j < 8; j++) {
            float4 v4 = sV[st][j][tx];
            float vs[4] = {v4.x, v4.y, v4.z, v4.w};
            const ulonglong2* av = (const ulonglong2*)(sArow + j * 20);
            ulonglong2 a0 = av[0], a1 = av[1], a2 = av[2], a3 = av[3];
#pragma unroll
            for (int dd = 0; dd < 4; dd++) {
                u64 v2 = pack2(vs[dd], vs[dd]);
                fma2(acc[dd * 8 + 0], a0.x, v2);
                fma2(acc[dd * 8 + 1], a0.y, v2);
                fma2(acc[dd * 8 + 2], a1.x, v2);
                fma2(acc[dd * 8 + 3], a1.y, v2);
                fma2(acc[dd * 8 + 4], a2.x, v2);
                fma2(acc[dd * 8 + 5], a2.y, v2);
                fma2(acc[dd * 8 + 6], a3.x, v2);
                fma2(acc[dd * 8 + 7], a3.y, v2);
            }
        }
    }

#pragma unroll
    for (int hp = 0; hp < 8; hp++) {
        float l0, h0x, l1, h1x, l2, h2x, l3, h3x;
        unpack2(acc[0 * 8 + hp], l0, h0x);
        unpack2(acc[1 * 8 + hp], l1, h1x);
        unpack2(acc[2 * 8 + hp], l2, h2x);
        unpack2(acc[3 * 8 + hp], l3, h3x);
        float4 olo = make_float4(l0, l1, l2, l3);
        float4 ohi = make_float4(h0x, h1x, h2x, h3x);
        *(float4*)(g_wp[seg] + ((size_t)b * HH + 2 * hp)     * DD + d0 + tx * 4) = olo;
        *(float4*)(g_wp[seg] + ((size_t)b * HH + 2 * hp + 1) * DD + d0 + tx * 4) = ohi;
    }
}

// ---------------------------------------------------------------------------
// Kernel F: out[b,c] += sum_{d in dsp-range(256)} w[b, c>>6, d] * wv[d, c]
// (w assembled on the fly from the 8 wpart partials)
// ---------------------------------------------------------------------------
__global__ __launch_bounds__(128) void k_oproj(const float* __restrict__ wv,
                                               float* __restrict__ out) {
    const int tx  = threadIdx.x;
    const int c0  = blockIdx.x * 128;
    const int b0  = blockIdx.y * 4;
    const int dsp = blockIdx.z;
    const int dr0 = dsp * 256;
    const int h0  = c0 >> 6;
    __shared__ __align__(16) float sw[4][2][256];

#pragma unroll
    for (int i = 0; i < 4; i++) {
        int fl = i * 128 + tx;
        int bb = fl >> 7, hh = (fl >> 6) & 1, d4 = fl & 63;
        size_t gidx = ((size_t)(b0 + bb) * HH + h0 + hh) * DD + dr0 + d4 * 4;
        float4 s = *(const float4*)(g_wp[0] + gidx);
#pragma unroll
        for (int p = 1; p < 8; p++) {
            float4 a = *(const float4*)(g_wp[p] + gidx);
            s.x += a.x; s.y += a.y; s.z += a.z; s.w += a.w;
        }
        *(float4*)&sw[bb][hh][d4 * 4] = s;
    }
    __syncthreads();

    const int hin = tx >> 6;
    u64 acc[4] = {0ull, 0ull, 0ull, 0ull};
    const float* wc = wv + (size_t)dr0 * DD + c0 + tx;
#pragma unroll 16
    for (int dd = 0; dd < 256; dd += 2) {
        float w0 = wc[(size_t)dd * DD];
        float w1 = wc[(size_t)(dd + 1) * DD];
        u64 w2 = pack2(w0, w1);
#pragma unroll
        for (int bb = 0; bb < 4; bb++) {
            u64 s2 = *(const u64*)&sw[bb][hin][dd];
            fma2(acc[bb], s2, w2);
        }
    }
#pragma unroll
    for (int bb = 0; bb < 4; bb++) {
        float lo, hi; unpack2(acc[bb], lo, hi);
        atomicAdd(&out[(size_t)(b0 + bb) * DD + c0 + tx], lo + hi);
    }
}

// ---------------------------------------------------------------------------
extern "C" void kernel_launch(void* const* d_in, const int* in_sizes, int n_in,
                              void* d_out, int out_size) {
    const float* query = (const float*)d_in[0];
    const float* key   = (const float*)d_in[1];
    const float* value = (const float*)d_in[2];
    const float* wq    = (const float*)d_in[3];
    const float* wk    = (const float*)d_in[4];
    const float* wv    = (const float*)d_in[5];
    float* out = (float*)d_out;

    k_qproj  <<<dim3(8, 8, 4),  128>>>(query, wq, out);
    k_uproj  <<<dim3(8, HH),    128>>>(wk);
    k_scores <<<dim3(16, BB),   64>>>(key);
    k_wpart  <<<dim3(2, 8, BB), 128>>>(value);   // 4th launch -> profiled
    k_oproj  <<<dim3(8, 8, 4),  128>>>(wv, out);
}